// round 16
// baseline (speedup 1.0000x reference)
#include <cuda_runtime.h>
#include <cuda_fp16.h>
#include <cstdint>

#define BB 4
#define NN 4096
#define LL 4104
#define DD 512
#define MM (BB*NN)   // 16384 GEMM rows

// ---------------- scratch (device globals; no allocations allowed) ----------
__device__ __half g_Ah[(size_t)MM*DD];          // conv output, fp16
__device__ __half g_Bh[DD*DD];                  // proj_w fp16
__device__ __half g_h2[(size_t)BB*LL*DD];       // proj output FP16, zero-padded rows [NN,LL)
__device__ float  g_p [BB*LL];                  // per-position score dot (atomic accum)
__device__ float4 g_S [BB*LL];                  // softmaxed block scores
__device__ float4 g_S2[BB*LL];                  // consensus-attended scores

// ---------------- PTX helpers (plain-sm_103-legal only) -----------------------
__device__ __forceinline__ uint32_t s2u(const void* p) {
    return (uint32_t)__cvta_generic_to_shared(p);
}
__device__ __forceinline__ void cpa16(uint32_t dst, const void* src) {
    asm volatile("cp.async.cg.shared.global [%0], [%1], 16;" :: "r"(dst), "l"(src));
}
__device__ __forceinline__ void cpa_commit() {
    asm volatile("cp.async.commit_group;" ::: "memory");
}
__device__ __forceinline__ void cpa_wait0() {
    asm volatile("cp.async.wait_group 0;" ::: "memory");
}
__device__ __forceinline__ void cpa_wait1() {
    asm volatile("cp.async.wait_group 1;" ::: "memory");
}
__device__ __forceinline__ void ldm4(uint32_t* r, uint32_t a) {
    asm volatile("ldmatrix.sync.aligned.m8n8.x4.shared.b16 {%0,%1,%2,%3}, [%4];"
                 : "=r"(r[0]), "=r"(r[1]), "=r"(r[2]), "=r"(r[3]) : "r"(a));
}
__device__ __forceinline__ void mma16816(float* d, const uint32_t* a, const uint32_t* b) {
    asm volatile(
        "mma.sync.aligned.m16n8k16.row.col.f32.f16.f16.f32 "
        "{%0,%1,%2,%3}, {%4,%5,%6,%7}, {%8,%9}, {%0,%1,%2,%3};"
        : "+f"(d[0]), "+f"(d[1]), "+f"(d[2]), "+f"(d[3])
        : "r"(a[0]), "r"(a[1]), "r"(a[2]), "r"(a[3]), "r"(b[0]), "r"(b[1]));
}
__device__ __forceinline__ float ex2(float x) {
    float r;
    asm("ex2.approx.ftz.f32 %0, %1;" : "=f"(r) : "f"(x));
    return r;
}
// ---- packed f32x2 (dual fp32 FMA pipe ops) ----
typedef unsigned long long ull;
__device__ __forceinline__ ull pk2(float lo, float hi) {
    ull r; asm("mov.b64 %0, {%1,%2};" : "=l"(r) : "f"(lo), "f"(hi)); return r;
}
__device__ __forceinline__ void upk2(float& lo, float& hi, ull v) {
    asm("mov.b64 {%0,%1}, %2;" : "=f"(lo), "=f"(hi) : "l"(v));
}
__device__ __forceinline__ ull fma2(ull a, ull b, ull c) {
    ull d; asm("fma.rn.f32x2 %0, %1, %2, %3;" : "=l"(d) : "l"(a), "l"(b), "l"(c)); return d;
}
__device__ __forceinline__ ull add2(ull a, ull b) {
    ull d; asm("add.rn.f32x2 %0, %1, %2;" : "=l"(d) : "l"(a), "l"(b)); return d;
}

// ---------------- kernel A: conv (16 pos/block, sliding window) + prep -------
#define CPOS 16
#define NCONVBLK (BB * NN / CPOS)    // 1024
#define NSPLIT (DD*DD)               // 262144
#define PADH (BB*8*DD)               // 16384
#define PADP (BB*LL)                 // 16416
#define PREP_TOT (NSPLIT + PADH + PADP)
#define NPREPBLK ((PREP_TOT + 127) / 128)   // 2304

__global__ __launch_bounds__(128) void conv_prep_kernel(
    const int* __restrict__ x, const float* __restrict__ emb,
    const float* __restrict__ cw, const float* __restrict__ cb,
    const float* __restrict__ W)
{
    int blk = blockIdx.x;
    if (blk >= NCONVBLK) {
        // ---- prep part ----
        int t = (blk - NCONVBLK) * 128 + threadIdx.x;
        if (t < NSPLIT) {
            g_Bh[t] = __float2half_rn(W[t]);
        } else if (t < NSPLIT + PADH) {
            int u = t - NSPLIT;
            int b = u / (8 * DD);
            int r = (u / DD) % 8;
            int d = u % DD;
            g_h2[((size_t)b * LL + NN + r) * DD + d] = __float2half_rn(0.0f);
        } else if (t < PREP_TOT) {
            g_p[t - NSPLIT - PADH] = 0.0f;
        }
        return;
    }

    // ---- conv part ----
    int b  = blk >> 8;                 // 256 blocks per batch row
    int i0 = (blk & 255) * CPOS;
    int d  = threadIdx.x * 4;

    __shared__ int toks[CPOS + 3];
    if (threadIdx.x < CPOS + 3) {
        int j = i0 + threadIdx.x;
        toks[threadIdx.x] = (j < NN) ? x[b * NN + j] : -1;
    }
    __syncthreads();

    float4 bv = *(const float4*)(cb + d);
    float4 w0 = *(const float4*)(cw + (d + 0) * 4);
    float4 w1 = *(const float4*)(cw + (d + 1) * 4);
    float4 w2 = *(const float4*)(cw + (d + 2) * 4);
    float4 w3 = *(const float4*)(cw + (d + 3) * 4);
    const float* pw0 = (const float*)&w0;
    const float* pw1 = (const float*)&w1;
    const float* pw2 = (const float*)&w2;
    const float* pw3 = (const float*)&w3;

    auto ldtok = [&](int s) -> float4 {
        int tok = toks[s];
        if (tok >= 0) return *(const float4*)(emb + (size_t)tok * DD + d);
        return make_float4(0.f, 0.f, 0.f, 0.f);
    };

    float4 win[4];
    win[0] = ldtok(0);
    win[1] = ldtok(1);
    win[2] = ldtok(2);

    __half* dst = g_Ah + ((size_t)(b * NN + i0)) * DD + d;

    #pragma unroll
    for (int p = 0; p < CPOS; p++) {
        win[(p + 3) & 3] = ldtok(p + 3);
        float4 acc = bv;
        #pragma unroll
        for (int k = 0; k < 4; k++) {
            float4 e = win[(p + k) & 3];
            acc.x += e.x * pw0[k];
            acc.y += e.y * pw1[k];
            acc.z += e.z * pw2[k];
            acc.w += e.w * pw3[k];
        }
        __half2 h01 = __halves2half2(__float2half_rn(acc.x), __float2half_rn(acc.y));
        __half2 h23 = __halves2half2(__float2half_rn(acc.z), __float2half_rn(acc.w));
        uint2 uh;
        uh.x = *(uint32_t*)&h01; uh.y = *(uint32_t*)&h23;
        *(uint2*)(dst + (size_t)p * DD) = uh;
    }
}

// ---------------- kernel B: mma.sync plain-fp16 GEMM (3 CTAs/SM) -------------
#define GBM 128
#define GBN 64
#define GBK 32
#define NKIT (DD / GBK)            // 16 k-iterations
#define RSTRIDE 80                 // smem row stride bytes (64B data + 16B pad)
#define ARR_A (128 * RSTRIDE)      // 10240
#define ARR_B (64 * RSTRIDE)       // 5120
#define BUF_BYTES (ARR_A + ARR_B)      // 15360 (Ah, Bh)
#define SM_TOTAL  (2 * BUF_BYTES)      // 30720 -> 3 CTAs/SM = 92KB smem

__global__ __launch_bounds__(256, 3)
void gemm_mma_kernel(const float* __restrict__ bias, const float* __restrict__ sw)
{
    extern __shared__ __align__(128) char smem[];
    const uint32_t su = s2u(smem);
    const int tid = threadIdx.x;
    const int wid = tid >> 5, lane = tid & 31;
    const int wm = wid >> 2, wn = wid & 3;      // 2(M) x 4(N) warp grid
    const int bn = blockIdx.x;                  // 0..7
    const int bm = blockIdx.y;                  // 0..127
    const int m0 = bm * GBM;
    const int n0 = bn * GBN;

    float acc[4][2][4];
    #pragma unroll
    for (int mt = 0; mt < 4; mt++)
        #pragma unroll
        for (int nt = 0; nt < 2; nt++)
            #pragma unroll
            for (int r = 0; r < 4; r++) acc[mt][nt][r] = 0.0f;

    // ---- async tile loader ----
    auto load_tiles = [&](int buf, int k0) {
        uint32_t dbase = su + buf * BUF_BYTES;
        #pragma unroll
        for (int t = 0; t < 2; t++) {
            int i = t * 256 + tid;          // 0..511
            int row = i >> 2, col = i & 3;
            uint32_t doff = row * RSTRIDE + col * 16;
            size_t ga = (size_t)(m0 + row) * DD + k0 + col * 8;
            cpa16(dbase + doff, g_Ah + ga);
        }
        {
            int row = tid >> 2, col = tid & 3;
            uint32_t doff = row * RSTRIDE + col * 16;
            size_t gb = (size_t)(n0 + row) * DD + k0 + col * 8;
            cpa16(dbase + ARR_A + doff, g_Bh + gb);
        }
    };

    load_tiles(0, 0);
    cpa_commit();
    load_tiles(1, GBK);
    cpa_commit();

    const uint32_t a_off = (uint32_t)(wm * 64 + (lane & 15)) * RSTRIDE + ((lane >> 4) * 16);
    const uint32_t b_off = (uint32_t)(wn * 16 + ((lane >> 4) & 1) * 8 + (lane & 7)) * RSTRIDE
                         + (((lane >> 3) & 1) * 16) + ARR_A;

    #pragma unroll 2
    for (int c = 0; c < NKIT; c++) {
        if (c + 1 < NKIT) cpa_wait1(); else cpa_wait0();
        __syncthreads();

        uint32_t base = su + (c & 1) * BUF_BYTES;
        uint32_t aA = base + a_off;
        uint32_t aB = base + b_off;

        #pragma unroll
        for (int ks = 0; ks < 2; ks++) {
            uint32_t kso = ks * 32;         // 16 fp16 = 32B
            uint32_t ah[4][4];
            uint32_t bhi[2][2];
            #pragma unroll
            for (int mt = 0; mt < 4; mt++)
                ldm4(ah[mt], aA + mt * (16 * RSTRIDE) + kso);
            {
                uint32_t t4[4];
                ldm4(t4, aB + kso);
                bhi[0][0] = t4[0]; bhi[0][1] = t4[1];
                bhi[1][0] = t4[2]; bhi[1][1] = t4[3];
            }
            #pragma unroll
            for (int mt = 0; mt < 4; mt++) {
                #pragma unroll
                for (int nt = 0; nt < 2; nt++)
                    mma16816(acc[mt][nt], ah[mt], bhi[nt]);
            }
        }

        if (c + 2 < NKIT) {
            __syncthreads();            // all warps done reading buf c&1
            load_tiles(c & 1, (c + 2) * GBK);
            cpa_commit();
        }
    }

    // ---- epilogue: write h2 (fp16) + fold partial score dot (RED into g_p) ----
    const int row0 = m0 + wm * 64 + (lane >> 2);
    const int col0 = n0 + wn * 16 + (lane & 3) * 2;
    #pragma unroll
    for (int mt = 0; mt < 4; mt++) {
        int m1 = row0 + mt * 16;
        int b1 = m1 >> 12, i1 = m1 & (NN - 1);
        int m2 = m1 + 8;
        int b2 = m2 >> 12, i2 = m2 & (NN - 1);
        __half* d1 = g_h2 + ((size_t)b1 * LL + i1) * DD;
        __half* d2 = g_h2 + ((size_t)b2 * LL + i2) * DD;
        float p1 = 0.0f, p2 = 0.0f;
        #pragma unroll
        for (int nt = 0; nt < 2; nt++) {
            int n = col0 + nt * 8;
            float bi0 = __ldg(bias + n), bi1 = __ldg(bias + n + 1);
            float w0 = __ldg(sw + n),   w1 = __ldg(sw + n + 1);
            float2 o1 = make_float2(acc[mt][nt][0] + bi0, acc[mt][nt][1] + bi1);
            float2 o2 = make_float2(acc[mt][nt][2] + bi0, acc[mt][nt][3] + bi1);
            __half2 h1 = __float22half2_rn(o1);
            __half2 h2v = __float22half2_rn(o2);
            *(uint32_t*)(d1 + n) = *(uint32_t*)&h1;
            *(uint32_t*)(d2 + n) = *(uint32_t*)&h2v;
            p1 += o1.x * w0 + o1.y * w1;
            p2 += o2.x * w0 + o2.y * w1;
        }
        p1 += __shfl_xor_sync(0xffffffffu, p1, 1);
        p1 += __shfl_xor_sync(0xffffffffu, p1, 2);
        p2 += __shfl_xor_sync(0xffffffffu, p2, 1);
        p2 += __shfl_xor_sync(0xffffffffu, p2, 2);
        if ((lane & 3) == 0) {
            atomicAdd(g_p + b1 * LL + i1, p1);
            atomicAdd(g_p + b2 * LL + i2, p2);
        }
    }
}

// ---------------- kernel C2: block means + softmax over 4 scales -------------
__global__ __launch_bounds__(128) void scores_kernel()
{
    int idx = blockIdx.x * blockDim.x + threadIdx.x;
    if (idx >= BB * LL) return;
    int b = idx / LL, i = idx - b * LL;
    const float* pb = g_p + b * LL;

    float r0 = pb[i];
    int j2 = i & ~1;
    float r1 = 0.5f * (pb[j2] + pb[j2 + 1]);
    int j3 = (i / 3) * 3;
    float r2 = (pb[j3] + pb[j3 + 1] + pb[j3 + 2]) * (1.0f / 3.0f);
    int j4 = i & ~3;
    float r3 = 0.25f * (pb[j4] + pb[j4 + 1] + pb[j4 + 2] + pb[j4 + 3]);

    float mx = fmaxf(fmaxf(r0, r1), fmaxf(r2, r3));
    float e0 = __expf(r0 - mx), e1 = __expf(r1 - mx);
    float e2 = __expf(r2 - mx), e3 = __expf(r3 - mx);
    float inv = 1.0f / (e0 + e1 + e2 + e3);
    g_S[idx] = make_float4(e0 * inv, e1 * inv, e2 * inv, e3 * inv);
}

// ---------------- kernel D: consensus, f32x2 packed (2 i x 2 j per step) ----
// FMA pipe was the binder (~50K cyc/SMSP); fma.rn.f32x2 halves FMA-pipe slots.
// Each thread processes j-pairs (j, j+1); accumulators are f32x2 lanes,
// combined at the end.  exp via single-MUFU ex2; a3 = den - a0 - a1 - a2.
#define CONS_IPT 2
#define CONS_BI  (32 * CONS_IPT)     // 64 i's per block
#define LOG2E 1.4426950408889634f
__global__ __launch_bounds__(256) void consensus_kernel()
{
    int b = blockIdx.y;
    int it = threadIdx.x >> 3;       // 0..31
    int jt = threadIdx.x & 7;        // 0..7 (low lane bits -> shfl group)
    int ibase = blockIdx.x * CONS_BI + it;   // + p*32
    const float4* Sb = g_S + b * LL;

    __shared__ float4 tile[1024];

    ull c0p[CONS_IPT], c1p[CONS_IPT], c2p[CONS_IPT], cwp[CONS_IPT];
    ull den2[CONS_IPT], a0_2[CONS_IPT], a1_2[CONS_IPT], a2_2[CONS_IPT];
    #pragma unroll
    for (int p = 0; p < CONS_IPT; p++) {
        int i = ibase + p * 32;
        float4 si = make_float4(0.f, 0.f, 0.f, 0.f);
        if (i < LL) si = Sb[i];
        float cw = si.w * LOG2E;
        float c0 = si.x * LOG2E - cw;
        float c1 = si.y * LOG2E - cw;
        float c2 = si.z * LOG2E - cw;
        c0p[p] = pk2(c0, c0); c1p[p] = pk2(c1, c1);
        c2p[p] = pk2(c2, c2); cwp[p] = pk2(cw, cw);
        den2[p] = pk2(0.f, 0.f); a0_2[p] = pk2(0.f, 0.f);
        a1_2[p] = pk2(0.f, 0.f); a2_2[p] = pk2(0.f, 0.f);
    }

    for (int j0 = 0; j0 < LL; j0 += 1024) {
        int cnt = min(1024, LL - j0);           // always even
        __syncthreads();
        for (int t = threadIdx.x; t < cnt; t += blockDim.x) tile[t] = Sb[j0 + t];
        __syncthreads();
        for (int j = jt * 2; j < cnt; j += 16) {
            float4 sa = tile[j];
            float4 sb = tile[j + 1];
            ull xx = pk2(sa.x, sb.x);
            ull yy = pk2(sa.y, sb.y);
            ull zz = pk2(sa.z, sb.z);
            #pragma unroll
            for (int p = 0; p < CONS_IPT; p++) {
                ull t2 = fma2(c0p[p], xx, fma2(c1p[p], yy, fma2(c2p[p], zz, cwp[p])));
                float tlo, thi;
                upk2(tlo, thi, t2);
                ull e2 = pk2(ex2(tlo), ex2(thi));
                den2[p] = add2(den2[p], e2);
                a0_2[p] = fma2(e2, xx, a0_2[p]);
                a1_2[p] = fma2(e2, yy, a1_2[p]);
                a2_2[p] = fma2(e2, zz, a2_2[p]);
            }
        }
    }

    #pragma unroll
    for (int p = 0; p < CONS_IPT; p++) {
        float dl, dh, l0, h0, l1, h1, l2, h2;
        upk2(dl, dh, den2[p]);
        upk2(l0, h0, a0_2[p]);
        upk2(l1, h1, a1_2[p]);
        upk2(l2, h2, a2_2[p]);
        float den = dl + dh, a0 = l0 + h0, a1 = l1 + h1, a2 = l2 + h2;
        #pragma unroll
        for (int o = 1; o < 8; o <<= 1) {
            den += __shfl_xor_sync(0xffffffffu, den, o);
            a0  += __shfl_xor_sync(0xffffffffu, a0,  o);
            a1  += __shfl_xor_sync(0xffffffffu, a1,  o);
            a2  += __shfl_xor_sync(0xffffffffu, a2,  o);
        }
        if (jt == 0) {
            int i = ibase + p * 32;
            if (i < LL) {
                float inv = 1.0f / den;
                float a3 = den - a0 - a1 - a2;
                g_S2[b * LL + i] = make_float4(a0 * inv, a1 * inv, a2 * inv, a3 * inv);
            }
        }
    }
}

// ---------------- kernel E: fuse + downsample (h2 now fp16) ------------------
__global__ __launch_bounds__(128) void fuse_kernel(float* __restrict__ out)
{
    int b = blockIdx.y;
    int m = blockIdx.x;              // 0..1023
    int jbase = 4 * m - 2;

    __shared__ float w[8];
    if (threadIdx.x == 0) {
        float ww[8] = {0, 0, 0, 0, 0, 0, 0, 0};
        #pragma unroll
        for (int ii = 0; ii < 4; ii++) {
            int i = 4 * m + ii;
            float4 s = g_S2[b * LL + i];
            ww[i - jbase] += 0.25f * s.x;
            int j2 = i & ~1;
            float c2 = 0.25f * 0.5f * s.y;
            ww[j2 - jbase] += c2; ww[j2 + 1 - jbase] += c2;
            int j3 = (i / 3) * 3;
            float c3 = 0.25f * (1.0f / 3.0f) * s.z;
            ww[j3 - jbase] += c3; ww[j3 + 1 - jbase] += c3; ww[j3 + 2 - jbase] += c3;
            int j4 = i & ~3;
            float c4 = 0.25f * 0.25f * s.w;
            ww[j4 - jbase] += c4; ww[j4 + 1 - jbase] += c4;
            ww[j4 + 2 - jbase] += c4; ww[j4 + 3 - jbase] += c4;
        }
        #pragma unroll
        for (int r = 0; r < 8; r++) w[r] = ww[r];
    }
    __syncthreads();

    int d = threadIdx.x * 4;
    float4 acc = make_float4(0.f, 0.f, 0.f, 0.f);
    #pragma unroll
    for (int r = 0; r < 8; r++) {
        int j = jbase + r;
        if (j < 0) continue;
        float wr = w[r];
        const __half2* hp = (const __half2*)(g_h2 + ((size_t)b * LL + j) * DD + d);
        float2 f0 = __half22float2(hp[0]);
        float2 f1 = __half22float2(hp[1]);
        acc.x += wr * f0.x; acc.y += wr * f0.y;
        acc.z += wr * f1.x; acc.w += wr * f1.y;
    }
    *(float4*)(out + ((size_t)(b * 1024 + m)) * DD + d) = acc;
}

// ---------------- launch ------------------------------------------------------
extern "C" void kernel_launch(void* const* d_in, const int* in_sizes, int n_in,
                              void* d_out, int out_size)
{
    const int*   x       = (const int*)  d_in[0];
    const float* emb     = (const float*)d_in[1];
    const float* conv_w  = (const float*)d_in[2];
    const float* conv_b  = (const float*)d_in[3];
    const float* proj_w  = (const float*)d_in[4];
    const float* proj_b  = (const float*)d_in[5];
    const float* score_w = (const float*)d_in[6];
    (void)in_sizes; (void)n_in; (void)out_size;
    float* out = (float*)d_out;

    cudaFuncSetAttribute(gemm_mma_kernel,
                         cudaFuncAttributeMaxDynamicSharedMemorySize, SM_TOTAL);

    conv_prep_kernel<<<NCONVBLK + NPREPBLK, 128>>>(x, emb, conv_w, conv_b, proj_w);
    gemm_mma_kernel<<<dim3(DD / GBN, MM / GBM), 256, SM_TOTAL>>>(proj_b, score_w);
    scores_kernel<<<(BB * LL + 127) / 128, 128>>>();
    consensus_kernel<<<dim3((LL + CONS_BI - 1) / CONS_BI, BB), 256>>>();
    fuse_kernel<<<dim3(1024, BB), 128>>>(out);
}

// round 17
// speedup vs baseline: 1.2153x; 1.2153x over previous
#include <cuda_runtime.h>
#include <cuda_fp16.h>
#include <cstdint>

#define BB 4
#define NN 4096
#define LL 4104
#define DD 512
#define MM (BB*NN)   // 16384 GEMM rows

#define NMON 126     // monomials of degree <= 5 in 4 vars

// ---------------- scratch (device globals; no allocations allowed) ----------
__device__ __half g_Ah[(size_t)MM*DD];          // conv output, fp16
__device__ __half g_Bh[DD*DD];                  // proj_w fp16
__device__ __half g_h2[(size_t)BB*LL*DD];       // proj output FP16, zero-padded rows
__device__ float  g_p [BB*LL];                  // per-position score dot (atomic accum)
__device__ float4 g_S [BB*LL];                  // softmaxed block scores
__device__ float4 g_S2[BB*LL];                  // consensus-attended scores
__device__ float  g_m [BB][128];                // monomial moments (126 used, atomic accum)

// ---------------- PTX helpers (plain-sm_103-legal only) -----------------------
__device__ __forceinline__ uint32_t s2u(const void* p) {
    return (uint32_t)__cvta_generic_to_shared(p);
}
__device__ __forceinline__ void cpa16(uint32_t dst, const void* src) {
    asm volatile("cp.async.cg.shared.global [%0], [%1], 16;" :: "r"(dst), "l"(src));
}
__device__ __forceinline__ void cpa_commit() {
    asm volatile("cp.async.commit_group;" ::: "memory");
}
__device__ __forceinline__ void cpa_wait0() {
    asm volatile("cp.async.wait_group 0;" ::: "memory");
}
__device__ __forceinline__ void cpa_wait1() {
    asm volatile("cp.async.wait_group 1;" ::: "memory");
}
__device__ __forceinline__ void ldm4(uint32_t* r, uint32_t a) {
    asm volatile("ldmatrix.sync.aligned.m8n8.x4.shared.b16 {%0,%1,%2,%3}, [%4];"
                 : "=r"(r[0]), "=r"(r[1]), "=r"(r[2]), "=r"(r[3]) : "r"(a));
}
__device__ __forceinline__ void mma16816(float* d, const uint32_t* a, const uint32_t* b) {
    asm volatile(
        "mma.sync.aligned.m16n8k16.row.col.f32.f16.f16.f32 "
        "{%0,%1,%2,%3}, {%4,%5,%6,%7}, {%8,%9}, {%0,%1,%2,%3};"
        : "+f"(d[0]), "+f"(d[1]), "+f"(d[2]), "+f"(d[3])
        : "r"(a[0]), "r"(a[1]), "r"(a[2]), "r"(a[3]), "r"(b[0]), "r"(b[1]));
}

// graded index of monomial x^a y^b z^c w^d among all with a+b+c+d <= 5
__device__ __host__ constexpr int midx(int a, int b, int c, int d) {
    int idx = 0;
    for (int aa = 0; aa < a; aa++)
        idx += (8 - aa) * (7 - aa) * (6 - aa) / 6;     // C(8-aa,3)
    for (int bb = 0; bb < b; bb++) {
        int r = 5 - a - bb;
        idx += (r + 2) * (r + 1) / 2;                  // C(r+2,2)
    }
    for (int cc = 0; cc < c; cc++)
        idx += 6 - a - b - cc;                         // r+1
    return idx + d;
}
__device__ __host__ constexpr float fct(int n) {
    return n <= 1 ? 1.f : (n == 2 ? 2.f : (n == 3 ? 6.f : (n == 4 ? 24.f : 120.f)));
}

// ---------------- kernel A: conv (16 pos/block, sliding window) + prep -------
#define CPOS 16
#define NCONVBLK (BB * NN / CPOS)    // 1024
#define NSPLIT (DD*DD)               // 262144
#define PADH (BB*8*DD)               // 16384
#define PADP (BB*LL)                 // 16416
#define PADM (BB*128)                // 512  (g_m zeroing)
#define PREP_TOT (NSPLIT + PADH + PADP + PADM)
#define NPREPBLK ((PREP_TOT + 127) / 128)

__global__ __launch_bounds__(128) void conv_prep_kernel(
    const int* __restrict__ x, const float* __restrict__ emb,
    const float* __restrict__ cw, const float* __restrict__ cb,
    const float* __restrict__ W)
{
    int blk = blockIdx.x;
    if (blk >= NCONVBLK) {
        // ---- prep part ----
        int t = (blk - NCONVBLK) * 128 + threadIdx.x;
        if (t < NSPLIT) {
            g_Bh[t] = __float2half_rn(W[t]);
        } else if (t < NSPLIT + PADH) {
            int u = t - NSPLIT;
            int b = u / (8 * DD);
            int r = (u / DD) % 8;
            int d = u % DD;
            g_h2[((size_t)b * LL + NN + r) * DD + d] = __float2half_rn(0.0f);
        } else if (t < NSPLIT + PADH + PADP) {
            g_p[t - NSPLIT - PADH] = 0.0f;
        } else if (t < PREP_TOT) {
            ((float*)g_m)[t - NSPLIT - PADH - PADP] = 0.0f;
        }
        return;
    }

    // ---- conv part ----
    int b  = blk >> 8;                 // 256 blocks per batch row
    int i0 = (blk & 255) * CPOS;
    int d  = threadIdx.x * 4;

    __shared__ int toks[CPOS + 3];
    if (threadIdx.x < CPOS + 3) {
        int j = i0 + threadIdx.x;
        toks[threadIdx.x] = (j < NN) ? x[b * NN + j] : -1;
    }
    __syncthreads();

    float4 bv = *(const float4*)(cb + d);
    float4 w0 = *(const float4*)(cw + (d + 0) * 4);
    float4 w1 = *(const float4*)(cw + (d + 1) * 4);
    float4 w2 = *(const float4*)(cw + (d + 2) * 4);
    float4 w3 = *(const float4*)(cw + (d + 3) * 4);
    const float* pw0 = (const float*)&w0;
    const float* pw1 = (const float*)&w1;
    const float* pw2 = (const float*)&w2;
    const float* pw3 = (const float*)&w3;

    auto ldtok = [&](int s) -> float4 {
        int tok = toks[s];
        if (tok >= 0) return *(const float4*)(emb + (size_t)tok * DD + d);
        return make_float4(0.f, 0.f, 0.f, 0.f);
    };

    float4 win[4];
    win[0] = ldtok(0);
    win[1] = ldtok(1);
    win[2] = ldtok(2);

    __half* dst = g_Ah + ((size_t)(b * NN + i0)) * DD + d;

    #pragma unroll
    for (int p = 0; p < CPOS; p++) {
        win[(p + 3) & 3] = ldtok(p + 3);
        float4 acc = bv;
        #pragma unroll
        for (int k = 0; k < 4; k++) {
            float4 e = win[(p + k) & 3];
            acc.x += e.x * pw0[k];
            acc.y += e.y * pw1[k];
            acc.z += e.z * pw2[k];
            acc.w += e.w * pw3[k];
        }
        __half2 h01 = __halves2half2(__float2half_rn(acc.x), __float2half_rn(acc.y));
        __half2 h23 = __halves2half2(__float2half_rn(acc.z), __float2half_rn(acc.w));
        uint2 uh;
        uh.x = *(uint32_t*)&h01; uh.y = *(uint32_t*)&h23;
        *(uint2*)(dst + (size_t)p * DD) = uh;
    }
}

// ---------------- kernel B: mma.sync plain-fp16 GEMM (3 CTAs/SM) -------------
#define GBM 128
#define GBN 64
#define GBK 32
#define NKIT (DD / GBK)            // 16 k-iterations
#define RSTRIDE 80                 // smem row stride bytes (64B data + 16B pad)
#define ARR_A (128 * RSTRIDE)      // 10240
#define ARR_B (64 * RSTRIDE)       // 5120
#define BUF_BYTES (ARR_A + ARR_B)      // 15360 (Ah, Bh)
#define SM_TOTAL  (2 * BUF_BYTES)      // 30720 -> 3 CTAs/SM = 92KB smem

__global__ __launch_bounds__(256, 3)
void gemm_mma_kernel(const float* __restrict__ bias, const float* __restrict__ sw)
{
    extern __shared__ __align__(128) char smem[];
    const uint32_t su = s2u(smem);
    const int tid = threadIdx.x;
    const int wid = tid >> 5, lane = tid & 31;
    const int wm = wid >> 2, wn = wid & 3;      // 2(M) x 4(N) warp grid
    const int bn = blockIdx.x;                  // 0..7
    const int bm = blockIdx.y;                  // 0..127
    const int m0 = bm * GBM;
    const int n0 = bn * GBN;

    float acc[4][2][4];
    #pragma unroll
    for (int mt = 0; mt < 4; mt++)
        #pragma unroll
        for (int nt = 0; nt < 2; nt++)
            #pragma unroll
            for (int r = 0; r < 4; r++) acc[mt][nt][r] = 0.0f;

    // ---- async tile loader ----
    auto load_tiles = [&](int buf, int k0) {
        uint32_t dbase = su + buf * BUF_BYTES;
        #pragma unroll
        for (int t = 0; t < 2; t++) {
            int i = t * 256 + tid;          // 0..511
            int row = i >> 2, col = i & 3;
            uint32_t doff = row * RSTRIDE + col * 16;
            size_t ga = (size_t)(m0 + row) * DD + k0 + col * 8;
            cpa16(dbase + doff, g_Ah + ga);
        }
        {
            int row = tid >> 2, col = tid & 3;
            uint32_t doff = row * RSTRIDE + col * 16;
            size_t gb = (size_t)(n0 + row) * DD + k0 + col * 8;
            cpa16(dbase + ARR_A + doff, g_Bh + gb);
        }
    };

    load_tiles(0, 0);
    cpa_commit();
    load_tiles(1, GBK);
    cpa_commit();

    const uint32_t a_off = (uint32_t)(wm * 64 + (lane & 15)) * RSTRIDE + ((lane >> 4) * 16);
    const uint32_t b_off = (uint32_t)(wn * 16 + ((lane >> 4) & 1) * 8 + (lane & 7)) * RSTRIDE
                         + (((lane >> 3) & 1) * 16) + ARR_A;

    #pragma unroll 2
    for (int c = 0; c < NKIT; c++) {
        if (c + 1 < NKIT) cpa_wait1(); else cpa_wait0();
        __syncthreads();

        uint32_t base = su + (c & 1) * BUF_BYTES;
        uint32_t aA = base + a_off;
        uint32_t aB = base + b_off;

        #pragma unroll
        for (int ks = 0; ks < 2; ks++) {
            uint32_t kso = ks * 32;         // 16 fp16 = 32B
            uint32_t ah[4][4];
            uint32_t bhi[2][2];
            #pragma unroll
            for (int mt = 0; mt < 4; mt++)
                ldm4(ah[mt], aA + mt * (16 * RSTRIDE) + kso);
            {
                uint32_t t4[4];
                ldm4(t4, aB + kso);
                bhi[0][0] = t4[0]; bhi[0][1] = t4[1];
                bhi[1][0] = t4[2]; bhi[1][1] = t4[3];
            }
            #pragma unroll
            for (int mt = 0; mt < 4; mt++) {
                #pragma unroll
                for (int nt = 0; nt < 2; nt++)
                    mma16816(acc[mt][nt], ah[mt], bhi[nt]);
            }
        }

        if (c + 2 < NKIT) {
            __syncthreads();            // all warps done reading buf c&1
            load_tiles(c & 1, (c + 2) * GBK);
            cpa_commit();
        }
    }

    // ---- epilogue: write h2 (fp16) + fold partial score dot (RED into g_p) ----
    const int row0 = m0 + wm * 64 + (lane >> 2);
    const int col0 = n0 + wn * 16 + (lane & 3) * 2;
    #pragma unroll
    for (int mt = 0; mt < 4; mt++) {
        int m1 = row0 + mt * 16;
        int b1 = m1 >> 12, i1 = m1 & (NN - 1);
        int m2 = m1 + 8;
        int b2 = m2 >> 12, i2 = m2 & (NN - 1);
        __half* d1 = g_h2 + ((size_t)b1 * LL + i1) * DD;
        __half* d2 = g_h2 + ((size_t)b2 * LL + i2) * DD;
        float p1 = 0.0f, p2 = 0.0f;
        #pragma unroll
        for (int nt = 0; nt < 2; nt++) {
            int n = col0 + nt * 8;
            float bi0 = __ldg(bias + n), bi1 = __ldg(bias + n + 1);
            float w0 = __ldg(sw + n),   w1 = __ldg(sw + n + 1);
            float2 o1 = make_float2(acc[mt][nt][0] + bi0, acc[mt][nt][1] + bi1);
            float2 o2 = make_float2(acc[mt][nt][2] + bi0, acc[mt][nt][3] + bi1);
            __half2 h1 = __float22half2_rn(o1);
            __half2 h2v = __float22half2_rn(o2);
            *(uint32_t*)(d1 + n) = *(uint32_t*)&h1;
            *(uint32_t*)(d2 + n) = *(uint32_t*)&h2v;
            p1 += o1.x * w0 + o1.y * w1;
            p2 += o2.x * w0 + o2.y * w1;
        }
        p1 += __shfl_xor_sync(0xffffffffu, p1, 1);
        p1 += __shfl_xor_sync(0xffffffffu, p1, 2);
        p2 += __shfl_xor_sync(0xffffffffu, p2, 1);
        p2 += __shfl_xor_sync(0xffffffffu, p2, 2);
        if ((lane & 3) == 0) {
            atomicAdd(g_p + b1 * LL + i1, p1);
            atomicAdd(g_p + b2 * LL + i2, p2);
        }
    }
}

// ---------------- kernel C2: block means + softmax over 4 scales -------------
__global__ __launch_bounds__(128) void scores_kernel()
{
    int idx = blockIdx.x * blockDim.x + threadIdx.x;
    if (idx >= BB * LL) return;
    int b = idx / LL, i = idx - b * LL;
    const float* pb = g_p + b * LL;

    float r0 = pb[i];
    int j2 = i & ~1;
    float r1 = 0.5f * (pb[j2] + pb[j2 + 1]);
    int j3 = (i / 3) * 3;
    float r2 = (pb[j3] + pb[j3 + 1] + pb[j3 + 2]) * (1.0f / 3.0f);
    int j4 = i & ~3;
    float r3 = 0.25f * (pb[j4] + pb[j4 + 1] + pb[j4 + 2] + pb[j4 + 3]);

    float mx = fmaxf(fmaxf(r0, r1), fmaxf(r2, r3));
    float e0 = __expf(r0 - mx), e1 = __expf(r1 - mx);
    float e2 = __expf(r2 - mx), e3 = __expf(r3 - mx);
    float inv = 1.0f / (e0 + e1 + e2 + e3);
    g_S[idx] = make_float4(e0 * inv, e1 * inv, e2 * inv, e3 * inv);
}

// ---------------- kernel D1: monomial moments of S (deg <= 5) ----------------
// m_alpha = sum_j s_j^alpha for all |alpha| <= 5 (126 values per batch).
__global__ __launch_bounds__(256) void moments_kernel()
{
    int b = blockIdx.y;
    int tid = blockIdx.x * 256 + threadIdx.x;   // gridDim.x = 2 -> 512 threads/batch
    int lane = threadIdx.x & 31;
    const float4* Sb = g_S + b * LL;

    float mm[NMON];
    #pragma unroll
    for (int q = 0; q < NMON; q++) mm[q] = 0.f;

    for (int j = tid; j < LL; j += 512) {
        float4 s = Sb[j];
        float xp[6], yp[6], zp[6], wp[6];
        xp[0] = yp[0] = zp[0] = wp[0] = 1.f;
        #pragma unroll
        for (int q = 1; q < 6; q++) {
            xp[q] = xp[q-1] * s.x; yp[q] = yp[q-1] * s.y;
            zp[q] = zp[q-1] * s.z; wp[q] = wp[q-1] * s.w;
        }
        #pragma unroll
        for (int a = 0; a <= 5; a++)
            #pragma unroll
            for (int bb = 0; bb <= 5 - a; bb++)
                #pragma unroll
                for (int c = 0; c <= 5 - a - bb; c++)
                    #pragma unroll
                    for (int d = 0; d <= 5 - a - bb - c; d++)
                        mm[midx(a, bb, c, d)] += xp[a] * yp[bb] * zp[c] * wp[d];
    }

    // warp reduce + atomic to global
    #pragma unroll
    for (int q = 0; q < NMON; q++) {
        float v = mm[q];
        #pragma unroll
        for (int o = 16; o; o >>= 1) v += __shfl_xor_sync(0xffffffffu, v, o);
        if (lane == 0) atomicAdd(&g_m[b][q], v);
    }
}

// ---------------- kernel D2: consensus via degree-4 polynomial of exp -------
// e^t on [0,1] ~ sum_k C_k t^k (Chebyshev, max err ~3e-5); t = s_i . s_j.
// den_i  = sum_{|a|<=4} C_|a| mult(a) s_i^a m_a
// a_c,i  = sum_{|a|<=4} C_|a| mult(a) s_i^a m_{a+e_c};  a3 = den - a0 - a1 - a2
__global__ __launch_bounds__(128) void conseval_kernel()
{
    int b = blockIdx.y;
    int i = blockIdx.x * 128 + threadIdx.x;

    __shared__ float sm[NMON];
    if (threadIdx.x < NMON) sm[threadIdx.x] = g_m[b][threadIdx.x];
    __syncthreads();
    if (i >= LL) return;

    float4 s = g_S[b * LL + i];
    float xp[5], yp[5], zp[5], wp[5];
    xp[0] = yp[0] = zp[0] = wp[0] = 1.f;
    #pragma unroll
    for (int q = 1; q < 5; q++) {
        xp[q] = xp[q-1] * s.x; yp[q] = yp[q-1] * s.y;
        zp[q] = zp[q-1] * s.z; wp[q] = wp[q-1] * s.w;
    }

    const float C[5] = {1.0000260f, 0.9987215f, 0.5099573f, 0.1399966f, 0.0695533f};

    float den = 0.f, a0 = 0.f, a1 = 0.f, a2 = 0.f;
    #pragma unroll
    for (int a = 0; a <= 4; a++)
        #pragma unroll
        for (int bb = 0; bb <= 4 - a; bb++)
            #pragma unroll
            for (int c = 0; c <= 4 - a - bb; c++)
                #pragma unroll
                for (int d = 0; d <= 4 - a - bb - c; d++) {
                    const int k = a + bb + c + d;
                    const float mult = fct(k) / (fct(a) * fct(bb) * fct(c) * fct(d));
                    float mono = (C[k] * mult) * xp[a] * yp[bb] * zp[c] * wp[d];
                    den = fmaf(mono, sm[midx(a, bb, c, d)], den);
                    a0  = fmaf(mono, sm[midx(a + 1, bb, c, d)], a0);
                    a1  = fmaf(mono, sm[midx(a, bb + 1, c, d)], a1);
                    a2  = fmaf(mono, sm[midx(a, bb, c + 1, d)], a2);
                }

    float inv = 1.0f / den;
    float a3 = den - a0 - a1 - a2;
    g_S2[b * LL + i] = make_float4(a0 * inv, a1 * inv, a2 * inv, a3 * inv);
}

// ---------------- kernel E: fuse + downsample (h2 fp16) ----------------------
__global__ __launch_bounds__(128) void fuse_kernel(float* __restrict__ out)
{
    int b = blockIdx.y;
    int m = blockIdx.x;              // 0..1023
    int jbase = 4 * m - 2;

    __shared__ float w[8];
    if (threadIdx.x == 0) {
        float ww[8] = {0, 0, 0, 0, 0, 0, 0, 0};
        #pragma unroll
        for (int ii = 0; ii < 4; ii++) {
            int i = 4 * m + ii;
            float4 s = g_S2[b * LL + i];
            ww[i - jbase] += 0.25f * s.x;
            int j2 = i & ~1;
            float c2 = 0.25f * 0.5f * s.y;
            ww[j2 - jbase] += c2; ww[j2 + 1 - jbase] += c2;
            int j3 = (i / 3) * 3;
            float c3 = 0.25f * (1.0f / 3.0f) * s.z;
            ww[j3 - jbase] += c3; ww[j3 + 1 - jbase] += c3; ww[j3 + 2 - jbase] += c3;
            int j4 = i & ~3;
            float c4 = 0.25f * 0.25f * s.w;
            ww[j4 - jbase] += c4; ww[j4 + 1 - jbase] += c4;
            ww[j4 + 2 - jbase] += c4; ww[j4 + 3 - jbase] += c4;
        }
        #pragma unroll
        for (int r = 0; r < 8; r++) w[r] = ww[r];
    }
    __syncthreads();

    int d = threadIdx.x * 4;
    float4 acc = make_float4(0.f, 0.f, 0.f, 0.f);
    #pragma unroll
    for (int r = 0; r < 8; r++) {
        int j = jbase + r;
        if (j < 0) continue;
        float wr = w[r];
        const __half2* hp = (const __half2*)(g_h2 + ((size_t)b * LL + j) * DD + d);
        float2 f0 = __half22float2(hp[0]);
        float2 f1 = __half22float2(hp[1]);
        acc.x += wr * f0.x; acc.y += wr * f0.y;
        acc.z += wr * f1.x; acc.w += wr * f1.y;
    }
    *(float4*)(out + ((size_t)(b * 1024 + m)) * DD + d) = acc;
}

// ---------------- launch ------------------------------------------------------
extern "C" void kernel_launch(void* const* d_in, const int* in_sizes, int n_in,
                              void* d_out, int out_size)
{
    const int*   x       = (const int*)  d_in[0];
    const float* emb     = (const float*)d_in[1];
    const float* conv_w  = (const float*)d_in[2];
    const float* conv_b  = (const float*)d_in[3];
    const float* proj_w  = (const float*)d_in[4];
    const float* proj_b  = (const float*)d_in[5];
    const float* score_w = (const float*)d_in[6];
    (void)in_sizes; (void)n_in; (void)out_size;
    float* out = (float*)d_out;

    cudaFuncSetAttribute(gemm_mma_kernel,
                         cudaFuncAttributeMaxDynamicSharedMemorySize, SM_TOTAL);

    conv_prep_kernel<<<NCONVBLK + NPREPBLK, 128>>>(x, emb, conv_w, conv_b, proj_w);
    gemm_mma_kernel<<<dim3(DD / GBN, MM / GBM), 256, SM_TOTAL>>>(proj_b, score_w);
    scores_kernel<<<(BB * LL + 127) / 128, 128>>>();
    moments_kernel<<<dim3(2, BB), 256>>>();
    conseval_kernel<<<dim3((LL + 127) / 128, BB), 128>>>();
    fuse_kernel<<<dim3(1024, BB), 128>>>(out);
}